// round 2
// baseline (speedup 1.0000x reference)
#include <cuda_runtime.h>
#include <cstdint>

#define VOCAB   50257
#define BEAM    8
#define BSZ     64
#define K       16
#define NGRAM   4
#define STEPDIM 16
#define SPLIT   4
#define CHUNK   12565   // ceil(50257/4)
#define T1      256

// Partial top-16 lists: [row][beam][chunk][16] sorted descending by key.
__device__ unsigned long long g_scratch[BSZ * BEAM * SPLIT * K];

// Monotone float -> uint32 encode: a > b  <=>  enc(a) > enc(b)
__device__ __forceinline__ unsigned int enc_f32(float v) {
    unsigned int u = __float_as_uint(v);
    return (u & 0x80000000u) ? ~u : (u | 0x80000000u);
}

// Key = [enc(value):32 | ~flat_index:32]. Larger key = larger value, then
// smaller flat index (matches lax.top_k stable tie-break). Keys are unique.
__device__ __forceinline__ unsigned long long make_key(float v, unsigned int flat) {
    return ((unsigned long long)enc_f32(v) << 32) | (unsigned int)(~flat);
}

__global__ __launch_bounds__(T1) void partial_topk(
    const float* __restrict__ lprobs,
    const float* __restrict__ scores,
    const int*   __restrict__ mask,
    const int*   __restrict__ step_ptr)
{
    const int chunk = blockIdx.x;
    const int beam  = blockIdx.y;
    const int row   = blockIdx.z;
    const int tid   = threadIdx.x;
    const int bb    = row * BEAM + beam;

    unsigned long long* dst = g_scratch + ((size_t)bb * SPLIT + chunk) * K;
    const int step = step_ptr ? step_ptr[0] : 16;

    // step==0: only beam 0 participates (beam_size collapses to 1).
    if (step == 0 && beam != 0) {
        if (tid < K) dst[tid] = 0ull;   // -inf sentinel
        return;
    }

    const int* m = mask + bb * NGRAM;
    const bool keep = (m[0] + m[1] + m[2] + m[3]) == NGRAM;
    const float bias = (step == 0) ? 0.0f
                                   : scores[bb * STEPDIM + (step - 1)];
    const unsigned int flatbase = (unsigned int)beam * VOCAB;
    const int start = chunk * CHUNK;
    const int end   = min(VOCAB, start + CHUNK);

    if (!keep) {
        // Entire beam is constant (= bias): top-16 of this chunk is the first
        // 16 indices, already sorted descending by key. Zero memory traffic.
        if (tid < K) dst[tid] = make_key(bias, flatbase + (unsigned)(start + tid));
        return;
    }

    const float* lp = lprobs + (size_t)bb * VOCAB;

    unsigned long long best[K];
    #pragma unroll
    for (int i = 0; i < K; i++) best[i] = 0ull;
    unsigned long long curmin = 0ull;

    for (int i = start + tid; i < end; i += T1) {
        float v = lp[i] + bias;
        unsigned long long key = make_key(v, flatbase + (unsigned)i);
        if (key > curmin) {                 // fast-path reject (register compare)
            int p = K - 1;
            while (p > 0 && best[p - 1] < key) { best[p] = best[p - 1]; p--; }
            best[p] = key;
            curmin = best[K - 1];
        }
    }

    // Tournament merge of 256 sorted 16-lists -> one sorted 16-list (8 rounds).
    __shared__ unsigned long long sh[T1 * K];
    for (int s = T1 / 2; s >= 1; s >>= 1) {
        if (tid >= s && tid < 2 * s) {
            #pragma unroll
            for (int i = 0; i < K; i++) sh[tid * K + i] = best[i];
        }
        __syncthreads();
        if (tid < s) {
            unsigned long long oth[K], mg[K];
            #pragma unroll
            for (int i = 0; i < K; i++) oth[i] = sh[(tid + s) * K + i];
            int a = 0, b = 0;
            #pragma unroll
            for (int t = 0; t < K; t++)
                mg[t] = (best[a] >= oth[b]) ? best[a++] : oth[b++];
            #pragma unroll
            for (int t = 0; t < K; t++) best[t] = mg[t];
        }
        __syncthreads();
    }

    if (tid == 0) {
        #pragma unroll
        for (int i = 0; i < K; i++) dst[i] = best[i];
    }
}

// One warp per batch row: 32-way tournament over 32 sorted 16-lists.
__global__ __launch_bounds__(32) void merge_topk(float* __restrict__ out)
{
    const int row  = blockIdx.x;
    const int lane = threadIdx.x;

    __shared__ unsigned long long sh[BEAM * SPLIT * K];   // 512 keys
    __shared__ unsigned long long res[K];

    for (int i = lane; i < BEAM * SPLIT * K; i += 32)
        sh[i] = g_scratch[(size_t)row * BEAM * SPLIT * K + i];
    __syncwarp();

    // Each lane owns one sorted list; 16 rounds of warp-max tournament.
    int p = 0;
    unsigned long long head = sh[lane * K + 0];
    for (int t = 0; t < K; t++) {
        unsigned long long mx = head;
        #pragma unroll
        for (int o = 16; o > 0; o >>= 1) {
            unsigned long long other = __shfl_xor_sync(0xffffffffu, mx, o);
            if (other > mx) mx = other;
        }
        if (head == mx) {        // unique keys -> exactly one winner lane
            res[t] = mx;
            p++;
            head = (p < K) ? sh[lane * K + p] : 0ull;
        }
        __syncwarp();
    }
    __syncwarp();

    if (lane < K) {
        unsigned long long key = res[lane];
        unsigned int hi = (unsigned int)(key >> 32);
        unsigned int lo = (unsigned int)key;
        unsigned int u  = (hi & 0x80000000u) ? (hi ^ 0x80000000u) : ~hi;
        float val = __uint_as_float(u);
        unsigned int flat = ~lo;
        unsigned int bsel = flat / VOCAB;
        unsigned int vsel = flat % VOCAB;

        out[              row * K + lane] = val;            // scores_buf
        out[BSZ * K     + row * K + lane] = (float)vsel;    // indices_buf
        out[2 * BSZ * K + row * K + lane] = (float)bsel;    // beams_buf
    }
}

extern "C" void kernel_launch(void* const* d_in, const int* in_sizes, int n_in,
                              void* d_out, int out_size) {
    (void)in_sizes; (void)out_size;
    const float* lprobs = (const float*)d_in[0];
    const float* scores = (const float*)d_in[1];
    const int*   mask   = (const int*)d_in[2];
    const int*   step   = (n_in > 3) ? (const int*)d_in[3] : nullptr;

    dim3 g1(SPLIT, BEAM, BSZ);
    partial_topk<<<g1, T1>>>(lprobs, scores, mask, step);
    merge_topk<<<BSZ, 32>>>((float*)d_out);
}

// round 3
// speedup vs baseline: 1.0025x; 1.0025x over previous
#include <cuda_runtime.h>
#include <cstdint>

#define VOCAB   50257
#define BEAM    8
#define BSZ     64
#define K       16
#define NGRAM   4
#define STEPDIM 16
#define SPLIT   4
#define CHUNK   12565   // ceil(50257/4)
#define T1      256

// Partial top-16 lists: [row][beam][chunk][16] sorted descending by key.
__device__ unsigned long long g_scratch[BSZ * BEAM * SPLIT * K];

// Monotone float -> uint32 encode: a > b  <=>  enc(a) > enc(b)
__device__ __forceinline__ unsigned int enc_f32(float v) {
    unsigned int u = __float_as_uint(v);
    return (u & 0x80000000u) ? ~u : (u | 0x80000000u);
}

// Key = [enc(value):32 | ~flat_index:32]. Larger key = larger value, then
// smaller flat index (matches lax.top_k stable tie-break). Keys are unique.
__device__ __forceinline__ unsigned long long make_key(float v, unsigned int flat) {
    return ((unsigned long long)enc_f32(v) << 32) | (unsigned int)(~flat);
}

__global__ __launch_bounds__(T1) void partial_topk(
    const float* __restrict__ lprobs,
    const float* __restrict__ scores,
    const int*   __restrict__ mask,
    const int*   __restrict__ step_ptr)
{
    const int chunk = blockIdx.x;
    const int beam  = blockIdx.y;
    const int row   = blockIdx.z;
    const int tid   = threadIdx.x;
    const int bb    = row * BEAM + beam;

    unsigned long long* dst = g_scratch + ((size_t)bb * SPLIT + chunk) * K;
    const int step = step_ptr ? step_ptr[0] : 16;

    // step==0: only beam 0 participates (beam_size collapses to 1).
    if (step == 0 && beam != 0) {
        if (tid < K) dst[tid] = 0ull;   // -inf sentinel
        return;
    }

    const int* m = mask + bb * NGRAM;
    const bool keep = (m[0] + m[1] + m[2] + m[3]) == NGRAM;
    const float bias = (step == 0) ? 0.0f
                                   : scores[bb * STEPDIM + (step - 1)];
    const unsigned int flatbase = (unsigned int)beam * VOCAB;
    const int start = chunk * CHUNK;
    const int end   = min(VOCAB, start + CHUNK);

    if (!keep) {
        // Entire beam is constant (= bias): top-16 of this chunk is the first
        // 16 indices, already sorted descending by key. Zero memory traffic.
        if (tid < K) dst[tid] = make_key(bias, flatbase + (unsigned)(start + tid));
        return;
    }

    const float* lp = lprobs + (size_t)bb * VOCAB;

    unsigned long long best[K];
    #pragma unroll
    for (int i = 0; i < K; i++) best[i] = 0ull;
    unsigned long long curmin = 0ull;

    for (int i = start + tid; i < end; i += T1) {
        float v = lp[i] + bias;
        unsigned long long key = make_key(v, flatbase + (unsigned)i);
        if (key > curmin) {                 // fast-path reject (register compare)
            int p = K - 1;
            while (p > 0 && best[p - 1] < key) { best[p] = best[p - 1]; p--; }
            best[p] = key;
            curmin = best[K - 1];
        }
    }

    // Tournament merge of 256 sorted 16-lists -> one sorted 16-list (8 rounds).
    __shared__ unsigned long long sh[T1 * K];
    for (int s = T1 / 2; s >= 1; s >>= 1) {
        if (tid >= s && tid < 2 * s) {
            #pragma unroll
            for (int i = 0; i < K; i++) sh[tid * K + i] = best[i];
        }
        __syncthreads();
        if (tid < s) {
            unsigned long long oth[K], mg[K];
            #pragma unroll
            for (int i = 0; i < K; i++) oth[i] = sh[(tid + s) * K + i];
            int a = 0, b = 0;
            #pragma unroll
            for (int t = 0; t < K; t++)
                mg[t] = (best[a] >= oth[b]) ? best[a++] : oth[b++];
            #pragma unroll
            for (int t = 0; t < K; t++) best[t] = mg[t];
        }
        __syncthreads();
    }

    if (tid == 0) {
        #pragma unroll
        for (int i = 0; i < K; i++) dst[i] = best[i];
    }
}

// One warp per batch row: 32-way tournament over 32 sorted 16-lists.
__global__ __launch_bounds__(32) void merge_topk(float* __restrict__ out)
{
    const int row  = blockIdx.x;
    const int lane = threadIdx.x;

    __shared__ unsigned long long sh[BEAM * SPLIT * K];   // 512 keys
    __shared__ unsigned long long res[K];

    for (int i = lane; i < BEAM * SPLIT * K; i += 32)
        sh[i] = g_scratch[(size_t)row * BEAM * SPLIT * K + i];
    __syncwarp();

    // Each lane owns one sorted list; 16 rounds of warp-max tournament.
    int p = 0;
    unsigned long long head = sh[lane * K + 0];
    for (int t = 0; t < K; t++) {
        unsigned long long mx = head;
        #pragma unroll
        for (int o = 16; o > 0; o >>= 1) {
            unsigned long long other = __shfl_xor_sync(0xffffffffu, mx, o);
            if (other > mx) mx = other;
        }
        if (head == mx) {        // unique keys -> exactly one winner lane
            res[t] = mx;
            p++;
            head = (p < K) ? sh[lane * K + p] : 0ull;
        }
        __syncwarp();
    }
    __syncwarp();

    if (lane < K) {
        unsigned long long key = res[lane];
        unsigned int hi = (unsigned int)(key >> 32);
        unsigned int lo = (unsigned int)key;
        unsigned int u  = (hi & 0x80000000u) ? (hi ^ 0x80000000u) : ~hi;
        float val = __uint_as_float(u);
        unsigned int flat = ~lo;
        unsigned int bsel = flat / VOCAB;
        unsigned int vsel = flat % VOCAB;

        out[              row * K + lane] = val;            // scores_buf
        out[BSZ * K     + row * K + lane] = (float)vsel;    // indices_buf
        out[2 * BSZ * K + row * K + lane] = (float)bsel;    // beams_buf
    }
}

extern "C" void kernel_launch(void* const* d_in, const int* in_sizes, int n_in,
                              void* d_out, int out_size) {
    (void)in_sizes; (void)out_size;
    const float* lprobs = (const float*)d_in[0];
    const float* scores = (const float*)d_in[1];
    const int*   mask   = (const int*)d_in[2];
    const int*   step   = (n_in > 3) ? (const int*)d_in[3] : nullptr;

    dim3 g1(SPLIT, BEAM, BSZ);
    partial_topk<<<g1, T1>>>(lprobs, scores, mask, step);
    merge_topk<<<BSZ, 32>>>((float*)d_out);
}

// round 8
// speedup vs baseline: 4.4746x; 4.4632x over previous
#include <cuda_runtime.h>

#define VOCAB   50257
#define BEAM    8
#define BSZ     64
#define K       16
#define NGRAM   4
#define STEPDIM 16
#define SPLIT   8
#define CHUNK   6283    // ceil(50257/8)
#define T1      256

typedef unsigned long long ull;

// Partial top-16 lists: [row][beam][chunk][16], each sorted descending by key.
__device__ ull g_scratch[BSZ * BEAM * SPLIT * K];

// Monotone float -> uint32 encode: a > b  <=>  enc(a) > enc(b)
__device__ __forceinline__ unsigned int enc_f32(float v) {
    unsigned int u = __float_as_uint(v);
    return (u & 0x80000000u) ? ~u : (u | 0x80000000u);
}
// Key = [enc(value):32 | ~flat_index:32]: larger key = larger value, then
// smaller flat index (lax.top_k stable tie-break). Keys are unique per row.
__device__ __forceinline__ ull make_key(float v, unsigned int flat) {
    return ((ull)enc_f32(v) << 32) | (unsigned int)(~flat);
}

// Sort a bitonic 16-sequence descending. Fully static indexing -> registers.
__device__ __forceinline__ void bitonic16_desc(ull v[K]) {
    #pragma unroll
    for (int d = 8; d >= 1; d >>= 1) {
        #pragma unroll
        for (int i = 0; i < K; i++) {
            if ((i & d) == 0) {          // compile-time predicate
                ull a = v[i], b = v[i | d];
                v[i]     = a > b ? a : b;
                v[i | d] = a > b ? b : a;
            }
        }
    }
}

// Merge own sorted-desc 16-list with xor-partner lane's: top-16 of the union,
// sorted desc. Both partners compute the identical result.
__device__ __forceinline__ void warp_merge_round(ull v[K], int o) {
    ull other[K];
    #pragma unroll
    for (int i = 0; i < K; i++)
        other[i] = __shfl_xor_sync(0xffffffffu, v[K - 1 - i], o);
    #pragma unroll
    for (int i = 0; i < K; i++)
        v[i] = v[i] > other[i] ? v[i] : other[i];
    bitonic16_desc(v);
}

// Register insert into sorted-desc 16-list (static indexing, no branches).
__device__ __forceinline__ void insert16(ull best[K], ull key) {
    ull x = key;
    #pragma unroll
    for (int j = 0; j < K; j++) {
        ull mx = best[j] > x ? best[j] : x;
        ull mn = best[j] > x ? x : best[j];
        best[j] = mx;
        x = mn;
    }
}

__global__ __launch_bounds__(T1) void partial_topk(
    const float* __restrict__ lprobs,
    const float* __restrict__ scores,
    const int*   __restrict__ mask,
    const int*   __restrict__ step_ptr)
{
    const int chunk = blockIdx.x;
    const int beam  = blockIdx.y;
    const int row   = blockIdx.z;
    const int tid   = threadIdx.x;
    const int bb    = row * BEAM + beam;

    ull* dst = g_scratch + ((size_t)bb * SPLIT + chunk) * K;
    const int step = step_ptr ? step_ptr[0] : STEPDIM;

    if (step == 0 && beam != 0) {              // beam collapses to 1 at step 0
        if (tid < K) dst[tid] = 0ull;
        return;
    }

    const int* m = mask + bb * NGRAM;
    const bool keep = (m[0] + m[1] + m[2] + m[3]) == NGRAM;
    const float bias = (step == 0) ? 0.0f : scores[bb * STEPDIM + (step - 1)];
    const unsigned int flatbase = (unsigned)beam * VOCAB;
    const int start = chunk * CHUNK;
    const int end   = min(VOCAB, start + CHUNK);

    if (!keep) {
        // Constant beam (= bias): chunk top-16 = first 16 indices, already
        // sorted desc by key. Zero lprobs traffic.
        if (tid < K) dst[tid] = make_key(bias, flatbase + (unsigned)(start + tid));
        return;
    }

    const float* lp = lprobs + (size_t)bb * VOCAB;

    ull best[K];
    #pragma unroll
    for (int i = 0; i < K; i++) best[i] = 0ull;
    ull curmin = 0ull;

    // 4-wide load batching for MLP; inserts are register-only.
    int i = start + tid;
    for (; i + 3 * T1 < end; i += 4 * T1) {
        float v0 = lp[i];
        float v1 = lp[i +     T1];
        float v2 = lp[i + 2 * T1];
        float v3 = lp[i + 3 * T1];
        ull k0 = make_key(v0 + bias, flatbase + (unsigned)(i));
        ull k1 = make_key(v1 + bias, flatbase + (unsigned)(i +     T1));
        ull k2 = make_key(v2 + bias, flatbase + (unsigned)(i + 2 * T1));
        ull k3 = make_key(v3 + bias, flatbase + (unsigned)(i + 3 * T1));
        if (k0 > curmin) { insert16(best, k0); curmin = best[K - 1]; }
        if (k1 > curmin) { insert16(best, k1); curmin = best[K - 1]; }
        if (k2 > curmin) { insert16(best, k2); curmin = best[K - 1]; }
        if (k3 > curmin) { insert16(best, k3); curmin = best[K - 1]; }
    }
    for (; i < end; i += T1) {
        ull key = make_key(lp[i] + bias, flatbase + (unsigned)i);
        if (key > curmin) { insert16(best, key); curmin = best[K - 1]; }
    }

    // Warp reduce: 5 shfl-xor bitonic merge rounds -> warp top-16 in all lanes.
    warp_merge_round(best, 1);
    warp_merge_round(best, 2);
    warp_merge_round(best, 4);
    warp_merge_round(best, 8);
    warp_merge_round(best, 16);

    // Cross-warp: 8 warp lists -> 1 via shared hop + 3 more rounds in warp 0.
    __shared__ ull sh[8 * K];
    const int warp = tid >> 5, lane = tid & 31;
    if (lane == 0) {
        #pragma unroll
        for (int q = 0; q < K; q++) sh[warp * K + q] = best[q];
    }
    __syncthreads();
    if (warp == 0) {
        ull v[K];
        const int src = lane & 7;          // lanes 8..31 hold duplicates (harmless)
        #pragma unroll
        for (int q = 0; q < K; q++) v[q] = sh[src * K + q];
        warp_merge_round(v, 1);
        warp_merge_round(v, 2);
        warp_merge_round(v, 4);
        if (lane == 0) {
            #pragma unroll
            for (int q = 0; q < K; q++) dst[q] = v[q];
        }
    }
}

// One warp per batch row, 8 rows per block. 64 sorted 16-lists -> top-16.
__global__ __launch_bounds__(256) void merge_topk(float* __restrict__ out)
{
    const int w    = threadIdx.x >> 5;
    const int lane = threadIdx.x & 31;
    const int row  = blockIdx.x * 8 + w;

    const ull* src = g_scratch + (size_t)row * BEAM * SPLIT * K;

    // Lane loads lists 2*lane and 2*lane+1 and pre-merges them (static idx).
    ull v[K];
    #pragma unroll
    for (int q = 0; q < K; q++) v[q] = src[(2 * lane) * K + q];
    {
        ull b[K];
        #pragma unroll
        for (int q = 0; q < K; q++) b[q] = src[(2 * lane + 1) * K + (K - 1 - q)];
        #pragma unroll
        for (int q = 0; q < K; q++) v[q] = v[q] > b[q] ? v[q] : b[q];
        bitonic16_desc(v);
    }

    warp_merge_round(v, 1);
    warp_merge_round(v, 2);
    warp_merge_round(v, 4);
    warp_merge_round(v, 8);
    warp_merge_round(v, 16);
    // All lanes now hold the row's top-16 sorted desc.

    __shared__ ull sh[8][K];
    if (lane == 0) {
        #pragma unroll
        for (int q = 0; q < K; q++) sh[w][q] = v[q];
    }
    __syncwarp();

    if (lane < K) {
        ull key = sh[w][lane];
        unsigned int hi = (unsigned)(key >> 32);
        unsigned int lo = (unsigned)key;
        unsigned int u  = (hi & 0x80000000u) ? (hi ^ 0x80000000u) : ~hi;
        float val = __uint_as_float(u);
        unsigned int flat = ~lo;
        unsigned int bsel = flat / VOCAB;
        unsigned int vsel = flat % VOCAB;

        out[              row * K + lane] = val;           // scores_buf
        out[BSZ * K     + row * K + lane] = (float)vsel;   // indices_buf
        out[2 * BSZ * K + row * K + lane] = (float)bsel;   // beams_buf
    }
}

extern "C" void kernel_launch(void* const* d_in, const int* in_sizes, int n_in,
                              void* d_out, int out_size) {
    (void)in_sizes; (void)out_size;
    const float* lprobs = (const float*)d_in[0];
    const float* scores = (const float*)d_in[1];
    const int*   mask   = (const int*)d_in[2];
    const int*   step   = (n_in > 3) ? (const int*)d_in[3] : nullptr;

    dim3 g1(SPLIT, BEAM, BSZ);
    partial_topk<<<g1, T1>>>(lprobs, scores, mask, step);
    merge_topk<<<BSZ / 8, 256>>>((float*)d_out);
}